// round 4
// baseline (speedup 1.0000x reference)
#include <cuda_runtime.h>
#include <cuda_bf16.h>

// SIREN MLP fused kernel, fp32 with packed f32x2 FMAs (sm_103a).
// N=262144 points, IN=3, HID=256, 4 hidden sine layers, OUT=3.
//
// One CTA processes TM=64 points. Activations h[64][256] (fp32) live in
// shared memory and are updated in place layer by layer. Hidden-layer GEMM:
// 256 threads as an 8x32 grid; each thread computes an 8(rows)x8(cols)
// microtile held as 32 packed f32x2 accumulators. Weights are staged in
// 16-wide k-slices into shared memory (k-major), with register prefetch of
// the next slice overlapping compute.

#define N_PTS   262144
#define HID     256
#define NL      4
#define TM      64
#define THREADS 256
#define OMEGA   30.0f

#define BK      16           // k-slice width staged in smem
#define NSTAGE  (HID / BK)   // 16 stages per layer

// smem layout (floats): h[TM*HID] | Wsh[BK*HID] | xs[TM*3 pad 256]
#define H_ELEMS   (TM * HID)          // 16384
#define W_ELEMS   (BK * HID)          // 4096
#define SMEM_FLTS (H_ELEMS + W_ELEMS + 256)
#define SMEM_BYTES (SMEM_FLTS * 4)

typedef unsigned long long ull;

__device__ __forceinline__ ull pack2(float lo) {
    ull r;
    asm("mov.b64 %0, {%1, %1};" : "=l"(r) : "f"(lo));
    return r;
}
__device__ __forceinline__ void unpack2(ull p, float& lo, float& hi) {
    asm("mov.b64 {%0, %1}, %2;" : "=f"(lo), "=f"(hi) : "l"(p));
}
__device__ __forceinline__ void fma2(ull& acc, ull a, ull b) {
    asm("fma.rn.f32x2 %0, %1, %2, %0;" : "+l"(acc) : "l"(a), "l"(b));
}

__global__ __launch_bounds__(THREADS, 2)
void siren_fused_kernel(const float* __restrict__ x,
                        const float* __restrict__ w_first,
                        const float* __restrict__ b_first,
                        const float* __restrict__ w_hidden,
                        const float* __restrict__ b_hidden,
                        const float* __restrict__ w_final,
                        const float* __restrict__ b_final,
                        float* __restrict__ out)
{
    extern __shared__ float smem[];
    float* h   = smem;                 // [TM][HID]
    float* Wsh = smem + H_ELEMS;       // [BK][HID] k-major
    float* xs  = smem + H_ELEMS + W_ELEMS;  // [TM][3]

    const int tid = threadIdx.x;
    const int p0  = blockIdx.x * TM;

    // ---- load x tile (64 x 3 = 192 floats) ----
    if (tid < TM * 3) xs[tid] = x[p0 * 3 + tid];
    __syncthreads();

    // ---- first layer: h = sin(30 * (x @ Wf^T + bf)) ----
    #pragma unroll 4
    for (int idx = tid; idx < TM * HID; idx += THREADS) {
        const int r = idx >> 8;      // point row
        const int c = idx & 255;     // hidden unit
        float z = b_first[c];
        z = fmaf(w_first[c * 3 + 0], xs[r * 3 + 0], z);
        z = fmaf(w_first[c * 3 + 1], xs[r * 3 + 1], z);
        z = fmaf(w_first[c * 3 + 2], xs[r * 3 + 2], z);
        h[r * HID + c] = sinf(OMEGA * z);
    }
    __syncthreads();

    // ---- hidden layers ----
    const int tx = tid & 31;      // column group: cols [tx*8, tx*8+8)
    const int ty = tid >> 5;      // row group:    rows [ty*8, ty*8+8)
    const int r0 = ty * 8;
    const int c0 = tx * 8;

    for (int l = 0; l < NL; ++l) {
        const float* W = w_hidden + l * (HID * HID);  // [out=256][in=256]
        const float* Wrow = W + tid * HID;            // this thread stages out-row `tid`

        // init accumulators with bias (pairs of adjacent columns)
        ull acc[32];
        {
            const ull* b64 = (const ull*)(b_hidden + l * HID);
            #pragma unroll
            for (int cc = 0; cc < 4; ++cc) {
                const ull bp = b64[tx * 4 + cc];
                #pragma unroll
                for (int j = 0; j < 8; ++j) acc[j * 4 + cc] = bp;
            }
        }

        // prefetch stage 0 of W into registers
        float4 pre[4];
        #pragma unroll
        for (int q = 0; q < 4; ++q)
            pre[q] = *(const float4*)(Wrow + 0 + q * 4);

        for (int s = 0; s < NSTAGE; ++s) {
            __syncthreads();   // previous stage's Wsh readers are done
            // store prefetched slice: Wsh[kk][c=tid], kk = local k
            #pragma unroll
            for (int q = 0; q < 4; ++q) {
                Wsh[(q * 4 + 0) * HID + tid] = pre[q].x;
                Wsh[(q * 4 + 1) * HID + tid] = pre[q].y;
                Wsh[(q * 4 + 2) * HID + tid] = pre[q].z;
                Wsh[(q * 4 + 3) * HID + tid] = pre[q].w;
            }
            // issue prefetch for next stage (overlaps with compute below)
            if (s + 1 < NSTAGE) {
                const int kn = (s + 1) * BK;
                #pragma unroll
                for (int q = 0; q < 4; ++q)
                    pre[q] = *(const float4*)(Wrow + kn + q * 4);
            }
            __syncthreads();   // Wsh slice ready

            const int k0 = s * BK;
            #pragma unroll
            for (int kk = 0; kk < BK; ++kk) {
                const ull* wr = (const ull*)(Wsh + kk * HID);
                const ull b0 = wr[tx * 4 + 0];
                const ull b1 = wr[tx * 4 + 1];
                const ull b2 = wr[tx * 4 + 2];
                const ull b3 = wr[tx * 4 + 3];
                const float* hk = h + k0 + kk;
                #pragma unroll
                for (int j = 0; j < 8; ++j) {
                    const ull a2 = pack2(hk[(r0 + j) * HID]);  // warp-broadcast LDS
                    fma2(acc[j * 4 + 0], a2, b0);
                    fma2(acc[j * 4 + 1], a2, b1);
                    fma2(acc[j * 4 + 2], a2, b2);
                    fma2(acc[j * 4 + 3], a2, b3);
                }
            }
        }

        // activation + in-place writeback
        __syncthreads();   // everyone finished reading h for this layer
        #pragma unroll
        for (int j = 0; j < 8; ++j) {
            float2* hrow = (float2*)(h + (r0 + j) * HID + c0);
            #pragma unroll
            for (int cc = 0; cc < 4; ++cc) {
                float lo, hi;
                unpack2(acc[j * 4 + cc], lo, hi);
                float2 v;
                v.x = sinf(OMEGA * lo);
                v.y = sinf(OMEGA * hi);
                hrow[cc] = v;
            }
        }
        __syncthreads();
    }

    // ---- final linear layer: out[r][c] = h[r,:] . w_final[c,:] + b_final[c] ----
    if (tid < TM * 3) {
        const int r = tid / 3;
        const int c = tid % 3;
        const float4* hrow = (const float4*)(h + r * HID);
        const float4* wrow = (const float4*)(w_final + c * HID);
        float a0 = 0.f, a1 = 0.f, a2s = 0.f, a3 = 0.f;
        #pragma unroll
        for (int q = 0; q < HID / 4; ++q) {
            const float4 hv = hrow[q];
            const float4 wv = wrow[q];
            a0 = fmaf(hv.x, wv.x, a0);
            a1 = fmaf(hv.y, wv.y, a1);
            a2s = fmaf(hv.z, wv.z, a2s);
            a3 = fmaf(hv.w, wv.w, a3);
        }
        out[(p0 + r) * 3 + c] = (a0 + a1) + (a2s + a3) + b_final[c];
    }
}

extern "C" void kernel_launch(void* const* d_in, const int* in_sizes, int n_in,
                              void* d_out, int out_size)
{
    const float* x        = (const float*)d_in[0];
    const float* w_first  = (const float*)d_in[1];
    const float* b_first  = (const float*)d_in[2];
    const float* w_hidden = (const float*)d_in[3];
    const float* b_hidden = (const float*)d_in[4];
    const float* w_final  = (const float*)d_in[5];
    const float* b_final  = (const float*)d_in[6];
    float* out = (float*)d_out;

    cudaFuncSetAttribute(siren_fused_kernel,
                         cudaFuncAttributeMaxDynamicSharedMemorySize, SMEM_BYTES);

    siren_fused_kernel<<<N_PTS / TM, THREADS, SMEM_BYTES>>>(
        x, w_first, b_first, w_hidden, b_hidden, w_final, b_final, out);
}

// round 9
// speedup vs baseline: 1.4310x; 1.4310x over previous
#include <cuda_runtime.h>
#include <cuda_bf16.h>

// SIREN MLP fused kernel, fp32 + packed f32x2 FMAs (sm_103a).
// R5: conflict-free b-operand layout (column pairs strided 64/thread) +
//     paired broadcast a-loads — fixes R4's 8-way LDS bank conflict
//     (R4 measured: L1=85%, fma=48.6%, 4590us).
// R8: polynomial sine (Cody-Waite mod-pi + deg-11 Taylor). Arg range is
//     analytically bounded: |30z| <= ~47 -> k <= 15, total added error
//     <~5e-6 end-to-end vs 1e-3 budget.

#define N_PTS   262144
#define HID     256
#define NL      4
#define TM      64
#define THREADS 256
#define OMEGA   30.0f

#define BK      16
#define NSTAGE  (HID / BK)

#define H_ELEMS   (TM * HID)
#define W_ELEMS   (BK * HID)
#define SMEM_FLTS (H_ELEMS + W_ELEMS + 256)
#define SMEM_BYTES (SMEM_FLTS * 4)

typedef unsigned long long ull;

__device__ __forceinline__ ull pack2(float lo) {
    ull r;
    asm("mov.b64 %0, {%1, %1};" : "=l"(r) : "f"(lo));
    return r;
}
__device__ __forceinline__ void unpack2(ull p, float& lo, float& hi) {
    asm("mov.b64 {%0, %1}, %2;" : "=f"(lo), "=f"(hi) : "l"(p));
}
__device__ __forceinline__ void fma2(ull& acc, ull a, ull b) {
    asm("fma.rn.f32x2 %0, %1, %2, %0;" : "+l"(acc) : "l"(a), "l"(b));
}

// sin(x) for |x| <= ~50: reduce mod pi (2-step Cody-Waite), deg-11 Taylor
// on [-pi/2, pi/2], sign flip by parity of k. ~12 instr, FMA-pipe heavy.
__device__ __forceinline__ float fast_sin(float x) {
    const float k = rintf(x * 0.3183098861837907f);
    float r = fmaf(k, -3.14159274101257f, x);   // x - k*PI_HI
    r = fmaf(k, 8.742277657347586e-8f, r);      // - k*PI_LO (PI_LO negative)
    const float r2 = r * r;
    float p = fmaf(r2, -2.5052108e-8f, 2.7557319e-6f);
    p = fmaf(r2, p, -1.9841270e-4f);
    p = fmaf(r2, p, 8.3333333e-3f);
    p = fmaf(r2, p, -1.6666667e-1f);
    float s = fmaf(r2 * p, r, r);
    const int ki = (int)k;
    return __int_as_float(__float_as_int(s) ^ (ki << 31));
}

__global__ __launch_bounds__(THREADS, 2)
void siren_fused_kernel(const float* __restrict__ x,
                        const float* __restrict__ w_first,
                        const float* __restrict__ b_first,
                        const float* __restrict__ w_hidden,
                        const float* __restrict__ b_hidden,
                        const float* __restrict__ w_final,
                        const float* __restrict__ b_final,
                        float* __restrict__ out)
{
    extern __shared__ float smem[];
    float* h   = smem;                      // [TM][HID] canonical layout
    float* Wsh = smem + H_ELEMS;            // [BK][HID] k-major
    float* xs  = smem + H_ELEMS + W_ELEMS;  // [TM][3]

    const int tid = threadIdx.x;
    const int p0  = blockIdx.x * TM;

    // ---- load x tile ----
    if (tid < TM * 3) xs[tid] = x[p0 * 3 + tid];
    __syncthreads();

    // ---- first layer: h = sin(30 * (x @ Wf^T + bf)) ----
    #pragma unroll 4
    for (int idx = tid; idx < TM * HID; idx += THREADS) {
        const int r = idx >> 8;
        const int c = idx & 255;
        float z = b_first[c];
        z = fmaf(w_first[c * 3 + 0], xs[r * 3 + 0], z);
        z = fmaf(w_first[c * 3 + 1], xs[r * 3 + 1], z);
        z = fmaf(w_first[c * 3 + 2], xs[r * 3 + 2], z);
        h[r * HID + c] = fast_sin(OMEGA * z);
    }
    __syncthreads();

    // ---- hidden layers ----
    // Thread (ty,tx): rows [ty*8, ty*8+8); column PAIRS (2tx+64cc, +1), cc=0..3.
    // b-loads lane-contiguous LDS.64 (conflict-free); h layout canonical.
    const int tx = tid & 31;
    const int ty = tid >> 5;
    const int r0 = ty * 8;

    for (int l = 0; l < NL; ++l) {
        const float* W = w_hidden + l * (HID * HID);
        const float* Wrow = W + tid * HID;

        ull acc[32];
        {
            const ull* b64 = (const ull*)(b_hidden + l * HID);
            #pragma unroll
            for (int cc = 0; cc < 4; ++cc) {
                const ull bp = b64[tx + 32 * cc];
                #pragma unroll
                for (int j = 0; j < 8; ++j) acc[j * 4 + cc] = bp;
            }
        }

        float4 pre[4];
        #pragma unroll
        for (int q = 0; q < 4; ++q)
            pre[q] = *(const float4*)(Wrow + 0 + q * 4);

        for (int s = 0; s < NSTAGE; ++s) {
            __syncthreads();
            #pragma unroll
            for (int q = 0; q < 4; ++q) {
                Wsh[(q * 4 + 0) * HID + tid] = pre[q].x;
                Wsh[(q * 4 + 1) * HID + tid] = pre[q].y;
                Wsh[(q * 4 + 2) * HID + tid] = pre[q].z;
                Wsh[(q * 4 + 3) * HID + tid] = pre[q].w;
            }
            if (s + 1 < NSTAGE) {
                const int kn = (s + 1) * BK;
                #pragma unroll
                for (int q = 0; q < 4; ++q)
                    pre[q] = *(const float4*)(Wrow + kn + q * 4);
            }
            __syncthreads();

            const int k0 = s * BK;
            #pragma unroll
            for (int kk = 0; kk < BK; kk += 2) {
                const ull* wr0 = (const ull*)(Wsh + (kk + 0) * HID);
                const ull* wr1 = (const ull*)(Wsh + (kk + 1) * HID);
                const ull b00 = wr0[tx +  0], b01 = wr0[tx + 32];
                const ull b02 = wr0[tx + 64], b03 = wr0[tx + 96];
                const ull b10 = wr1[tx +  0], b11 = wr1[tx + 32];
                const ull b12 = wr1[tx + 64], b13 = wr1[tx + 96];
                const float* hk = h + k0 + kk;
                #pragma unroll
                for (int j = 0; j < 8; ++j) {
                    const float2 av = *(const float2*)(hk + (r0 + j) * HID);
                    const ull a0 = pack2(av.x);
                    const ull a1 = pack2(av.y);
                    fma2(acc[j * 4 + 0], a0, b00);
                    fma2(acc[j * 4 + 1], a0, b01);
                    fma2(acc[j * 4 + 2], a0, b02);
                    fma2(acc[j * 4 + 3], a0, b03);
                    fma2(acc[j * 4 + 0], a1, b10);
                    fma2(acc[j * 4 + 1], a1, b11);
                    fma2(acc[j * 4 + 2], a1, b12);
                    fma2(acc[j * 4 + 3], a1, b13);
                }
            }
        }

        // activation + in-place writeback
        __syncthreads();
        #pragma unroll
        for (int j = 0; j < 8; ++j) {
            float* hrow = h + (r0 + j) * HID + 2 * tx;
            #pragma unroll
            for (int cc = 0; cc < 4; ++cc) {
                float lo, hi;
                unpack2(acc[j * 4 + cc], lo, hi);
                float2 v;
                v.x = fast_sin(OMEGA * lo);
                v.y = fast_sin(OMEGA * hi);
                *(float2*)(hrow + 64 * cc) = v;
            }
        }
        __syncthreads();
    }

    // ---- final linear layer ----
    if (tid < TM * 3) {
        const int r = tid / 3;
        const int c = tid % 3;
        const float4* hrow = (const float4*)(h + r * HID);
        const float4* wrow = (const float4*)(w_final + c * HID);
        float a0 = 0.f, a1 = 0.f, a2s = 0.f, a3 = 0.f;
        #pragma unroll
        for (int q = 0; q < HID / 4; ++q) {
            const float4 hv = hrow[q];
            const float4 wv = wrow[q];
            a0 = fmaf(hv.x, wv.x, a0);
            a1 = fmaf(hv.y, wv.y, a1);
            a2s = fmaf(hv.z, wv.z, a2s);
            a3 = fmaf(hv.w, wv.w, a3);
        }
        out[(p0 + r) * 3 + c] = (a0 + a1) + (a2s + a3) + b_final[c];
    }
}

extern "C" void kernel_launch(void* const* d_in, const int* in_sizes, int n_in,
                              void* d_out, int out_size)
{
    const float* x        = (const float*)d_in[0];
    const float* w_first  = (const float*)d_in[1];
    const float* b_first  = (const float*)d_in[2];
    const float* w_hidden = (const float*)d_in[3];
    const float* b_hidden = (const float*)d_in[4];
    const float* w_final  = (const float*)d_in[5];
    const float* b_final  = (const float*)d_in[6];
    float* out = (float*)d_out;

    cudaFuncSetAttribute(siren_fused_kernel,
                         cudaFuncAttributeMaxDynamicSharedMemorySize, SMEM_BYTES);

    siren_fused_kernel<<<N_PTS / TM, THREADS, SMEM_BYTES>>>(
        x, w_first, b_first, w_hidden, b_hidden, w_final, b_final, out);
}